// round 8
// baseline (speedup 1.0000x reference)
#include <cuda_runtime.h>
#include <cstdint>

// Problem dims
#define T_STEPS 512
#define BATCH   64
#define INDIM   256
#define HID     512

// ---------------- Phase 1: xw = x @ W_ih^T + bias_ih + bias_hh ----------------
// C[m,n] = sum_k x[m,k] * W_ih[n,k],  m = t*64+b (32768), n = hidden (512), k = 256

__device__ float g_xw[(size_t)T_STEPS * BATCH * HID];   // 64 MB static scratch

#define BM 128
#define BN 128
#define BK 16
#define LDP 132   // padded m/n stride in floats (keeps 16B alignment, spreads banks)

__global__ void __launch_bounds__(256, 2)
xw_gemm_kernel(const float* __restrict__ x, const float* __restrict__ wih,
               const float* __restrict__ bih, const float* __restrict__ bhh)
{
    __shared__ float As[BK * LDP];   // [k][m]
    __shared__ float Bs[BK * LDP];   // [k][n]

    const int tid = threadIdx.x;
    const int mb = blockIdx.x * BM;
    const int nb = blockIdx.y * BN;

    const int tx = tid & 15;        // n dir
    const int ty = tid >> 4;        // m dir
    const int m0 = ty * 8;
    const int n0 = tx * 8;

    const int lrow = tid >> 2;          // 0..63
    const int lk   = (tid & 3) * 4;     // 0,4,8,12

    float acc[8][8];
#pragma unroll
    for (int i = 0; i < 8; ++i)
#pragma unroll
        for (int jj = 0; jj < 8; ++jj) acc[i][jj] = 0.f;

    for (int k0 = 0; k0 < INDIM; k0 += BK) {
        // load A (x rows) and B (W_ih rows) tiles, transposed into [k][row] layout
#pragma unroll
        for (int h = 0; h < 2; ++h) {
            const int row = lrow + h * 64;
            float4 a = *reinterpret_cast<const float4*>(x + (size_t)(mb + row) * INDIM + k0 + lk);
            As[(lk + 0) * LDP + row] = a.x;
            As[(lk + 1) * LDP + row] = a.y;
            As[(lk + 2) * LDP + row] = a.z;
            As[(lk + 3) * LDP + row] = a.w;
            float4 b = *reinterpret_cast<const float4*>(wih + (size_t)(nb + row) * INDIM + k0 + lk);
            Bs[(lk + 0) * LDP + row] = b.x;
            Bs[(lk + 1) * LDP + row] = b.y;
            Bs[(lk + 2) * LDP + row] = b.z;
            Bs[(lk + 3) * LDP + row] = b.w;
        }
        __syncthreads();

#pragma unroll
        for (int k = 0; k < BK; ++k) {
            float4 a0 = *reinterpret_cast<const float4*>(As + k * LDP + m0);
            float4 a1 = *reinterpret_cast<const float4*>(As + k * LDP + m0 + 4);
            float4 b0 = *reinterpret_cast<const float4*>(Bs + k * LDP + n0);
            float4 b1 = *reinterpret_cast<const float4*>(Bs + k * LDP + n0 + 4);
            float av[8] = {a0.x, a0.y, a0.z, a0.w, a1.x, a1.y, a1.z, a1.w};
            float bv[8] = {b0.x, b0.y, b0.z, b0.w, b1.x, b1.y, b1.z, b1.w};
#pragma unroll
            for (int i = 0; i < 8; ++i)
#pragma unroll
                for (int jj = 0; jj < 8; ++jj)
                    acc[i][jj] = fmaf(av[i], bv[jj], acc[i][jj]);
        }
        __syncthreads();
    }

    // epilogue: add biases, store
    float bia[8];
#pragma unroll
    for (int jj = 0; jj < 8; ++jj)
        bia[jj] = __ldg(bih + nb + n0 + jj) + __ldg(bhh + nb + n0 + jj);

#pragma unroll
    for (int i = 0; i < 8; ++i) {
        float4 o0, o1;
        o0.x = acc[i][0] + bia[0];
        o0.y = acc[i][1] + bia[1];
        o0.z = acc[i][2] + bia[2];
        o0.w = acc[i][3] + bia[3];
        o1.x = acc[i][4] + bia[4];
        o1.y = acc[i][5] + bia[5];
        o1.z = acc[i][6] + bia[6];
        o1.w = acc[i][7] + bia[7];
        float* dst = g_xw + (size_t)(mb + m0 + i) * HID + nb + n0;
        *reinterpret_cast<float4*>(dst)     = o0;
        *reinterpret_cast<float4*>(dst + 4) = o1;
    }
}

// ---------------- Phase 2: recurrence ----------------
// h_t[b,j] = relu(xw[t,b,j] + sum_k W_hh[j,k] * h_{t-1}[b,k])
// 16 clusters x 8 CTAs. Cluster = 4 batches; CTA rank r owns j in [r*64, r*64+64),
// with its W_hh slice k-major in SMEM (128 KB, stationary for all 512 steps).
// Per-step cross-CTA h exchange goes through d_out (which must be written anyway):
// STG -> barrier.cluster (release/acquire) -> __ldcg pull of 8 KB from L2.

#define CL_SIZE     8
#define JS          64
#define BSZ         4
#define RNN_CTAS    ((BATCH / BSZ) * CL_SIZE)   // 128
#define RNN_THREADS 256

#define SM_W   (HID * JS)        // 32768 floats: Wsh[k][j_local]
#define SM_H   (BSZ * HID)       // 2048  floats: hbuf[b][k]
#define SM_RED (4 * BSZ * JS)    // 1024  floats: red[kp][b][j]
#define RNN_SMEM_BYTES ((SM_W + SM_H + SM_RED) * 4)   // 143360

__global__ void __launch_bounds__(RNN_THREADS, 1) __cluster_dims__(CL_SIZE, 1, 1)
rnn_kernel(const float* __restrict__ whh, float* __restrict__ out)
{
    extern __shared__ float smem[];
    float* Wsh  = smem;             // [HID][JS]  k-major
    float* hbuf = smem + SM_W;      // [BSZ][HID]
    float* red  = hbuf + SM_H;      // [4][BSZ][JS]

    const int tid  = threadIdx.x;
    const int rank = blockIdx.x & (CL_SIZE - 1);   // j-group within cluster
    const int cl   = blockIdx.x >> 3;              // cluster id -> batch group
    const int j0   = rank * JS;
    const int b0   = cl * BSZ;

    // Load W_hh rows [j0, j0+64) into k-major SMEM: Wsh[k*64 + jl] = W[j0+jl][k]
#pragma unroll
    for (int i = 0; i < (JS * HID / 4) / RNN_THREADS; ++i) {   // 32 iters
        const int idx = tid + i * RNN_THREADS;
        const int jl  = idx >> 7;            // 128 float4 per row
        const int kc  = (idx & 127) * 4;
        float4 w = *reinterpret_cast<const float4*>(whh + (size_t)(j0 + jl) * HID + kc);
        Wsh[(kc + 0) * JS + jl] = w.x;
        Wsh[(kc + 1) * JS + jl] = w.y;
        Wsh[(kc + 2) * JS + jl] = w.z;
        Wsh[(kc + 3) * JS + jl] = w.w;
    }
    // h_{-1} = 0
    for (int i = tid; i < SM_H; i += RNN_THREADS) hbuf[i] = 0.f;

    const int kp    = tid >> 6;      // k-partition 0..3 (also local batch in tail)
    const int j     = tid & 63;      // local j
    const int kbase = kp * 128;
    const int gb    = b0 + kp;       // global batch this thread handles in tail

    float xw = g_xw[(size_t)gb * HID + j0 + j];   // xw for t=0
    __syncthreads();

    for (int t = 0; t < T_STEPS; ++t) {
        // partial sums over k in [kbase, kbase+128) for 4 batches
        float a0 = 0.f, a1 = 0.f, a2 = 0.f, a3 = 0.f;
        const float* hb0 = hbuf + 0 * HID + kbase;
        const float* hb1 = hbuf + 1 * HID + kbase;
        const float* hb2 = hbuf + 2 * HID + kbase;
        const float* hb3 = hbuf + 3 * HID + kbase;
        const float* wp  = Wsh + kbase * JS + j;

#pragma unroll 4
        for (int kk = 0; kk < 128; kk += 4) {
            float4 h0 = *reinterpret_cast<const float4*>(hb0 + kk);
            float4 h1 = *reinterpret_cast<const float4*>(hb1 + kk);
            float4 h2 = *reinterpret_cast<const float4*>(hb2 + kk);
            float4 h3 = *reinterpret_cast<const float4*>(hb3 + kk);
            float w;
            w = wp[(kk + 0) * JS];
            a0 = fmaf(w, h0.x, a0); a1 = fmaf(w, h1.x, a1);
            a2 = fmaf(w, h2.x, a2); a3 = fmaf(w, h3.x, a3);
            w = wp[(kk + 1) * JS];
            a0 = fmaf(w, h0.y, a0); a1 = fmaf(w, h1.y, a1);
            a2 = fmaf(w, h2.y, a2); a3 = fmaf(w, h3.y, a3);
            w = wp[(kk + 2) * JS];
            a0 = fmaf(w, h0.z, a0); a1 = fmaf(w, h1.z, a1);
            a2 = fmaf(w, h2.z, a2); a3 = fmaf(w, h3.z, a3);
            w = wp[(kk + 3) * JS];
            a0 = fmaf(w, h0.w, a0); a1 = fmaf(w, h1.w, a1);
            a2 = fmaf(w, h2.w, a2); a3 = fmaf(w, h3.w, a3);
        }

        // stash k-partials: red[kp][b][j]
        red[(kp * 4 + 0) * JS + j] = a0;
        red[(kp * 4 + 1) * JS + j] = a1;
        red[(kp * 4 + 2) * JS + j] = a2;
        red[(kp * 4 + 3) * JS + j] = a3;
        __syncthreads();

        // tail: this thread finalizes (batch kp, column j)
        float s = red[(0 * 4 + kp) * JS + j]
                + red[(1 * 4 + kp) * JS + j]
                + red[(2 * 4 + kp) * JS + j]
                + red[(3 * 4 + kp) * JS + j];
        float v = fmaxf(s + xw, 0.f);
        out[((size_t)t * BATCH + gb) * HID + j0 + j] = v;
        if (t == T_STEPS - 1)
            out[(size_t)T_STEPS * BATCH * HID + (size_t)gb * HID + j0 + j] = v;

        if (t + 1 < T_STEPS) {
            // release our h_t slice to cluster peers
            asm volatile("barrier.cluster.arrive.aligned;" ::: "memory");
            // independent prefetch between arrive and wait
            float nxw = g_xw[((size_t)(t + 1) * BATCH + gb) * HID + j0 + j];
            asm volatile("barrier.cluster.wait.aligned;" ::: "memory");

            // pull full h_t for our 4 batches from out[t] (L2-resident), bypass L1
            const int lb  = kp;            // local batch 0..3 (64 threads each)
            const int kk4 = j * 4;         // 0..252
            const float* src = out + ((size_t)t * BATCH + b0 + lb) * HID;
            float4 v0 = __ldcg(reinterpret_cast<const float4*>(src + kk4));
            float4 v1 = __ldcg(reinterpret_cast<const float4*>(src + kk4 + 256));
            *reinterpret_cast<float4*>(hbuf + lb * HID + kk4)       = v0;
            *reinterpret_cast<float4*>(hbuf + lb * HID + kk4 + 256) = v1;
            xw = nxw;
            __syncthreads();
        }
    }
}

// ---------------- launch ----------------
extern "C" void kernel_launch(void* const* d_in, const int* in_sizes, int n_in,
                              void* d_out, int out_size)
{
    (void)in_sizes; (void)n_in; (void)out_size;
    const float* x   = (const float*)d_in[0];
    const float* wih = (const float*)d_in[1];
    const float* whh = (const float*)d_in[2];
    const float* bih = (const float*)d_in[3];
    const float* bhh = (const float*)d_in[4];
    float* out = (float*)d_out;

    // Phase 1: big GEMM into g_xw
    dim3 g1((T_STEPS * BATCH) / BM, HID / BN);   // (256, 4)
    xw_gemm_kernel<<<g1, 256>>>(x, wih, bih, bhh);

    // Phase 2: clustered recurrence (idempotent attribute set; host-side, capture-safe)
    cudaFuncSetAttribute(rnn_kernel, cudaFuncAttributeMaxDynamicSharedMemorySize,
                         RNN_SMEM_BYTES);
    rnn_kernel<<<RNN_CTAS, RNN_THREADS, RNN_SMEM_BYTES>>>(whh, out);
}

// round 9
// speedup vs baseline: 1.3748x; 1.3748x over previous
#include <cuda_runtime.h>
#include <cstdint>

// Problem dims
#define T_STEPS 512
#define BATCH   64
#define INDIM   256
#define HID     512

// ---------------- f32x2 helpers (FFMA2 only reachable via PTX) ----------------
__device__ __forceinline__ unsigned long long pack2(float x, float y) {
    unsigned long long r;
    asm("mov.b64 %0, {%1,%2};" : "=l"(r) : "f"(x), "f"(y));
    return r;
}
__device__ __forceinline__ void unpack2(unsigned long long v, float& x, float& y) {
    asm("mov.b64 {%0,%1}, %2;" : "=f"(x), "=f"(y) : "l"(v));
}
__device__ __forceinline__ void fma2(unsigned long long& d, unsigned long long a,
                                     unsigned long long b) {
    asm("fma.rn.f32x2 %0, %1, %2, %0;" : "+l"(d) : "l"(a), "l"(b));
}

// ---------------- Phase 1: xw = x @ W_ih^T + bias_ih + bias_hh ----------------
// C[m,n] = sum_k x[m,k] * W_ih[n,k],  m = t*64+b (32768), n (512), k (256)

__device__ float g_xw[(size_t)T_STEPS * BATCH * HID];   // 64 MB static scratch

#define BM 128
#define BN 128
#define BK 16
#define LDP 132   // padded row stride in floats (16B aligned: 132*4=528=33*16)

__global__ void __launch_bounds__(256, 2)
xw_gemm_kernel(const float* __restrict__ x, const float* __restrict__ wih,
               const float* __restrict__ bih, const float* __restrict__ bhh)
{
    __shared__ float As[BK * LDP];   // [k][m]
    __shared__ float Bs[BK * LDP];   // [k][n]

    const int tid = threadIdx.x;
    const int mb = blockIdx.x * BM;
    const int nb = blockIdx.y * BN;

    const int tx = tid & 15;        // n dir
    const int ty = tid >> 4;        // m dir
    const int m0 = ty * 8;
    const int n0 = tx * 8;

    const int lrow = tid >> 2;          // 0..63
    const int lk   = (tid & 3) * 4;     // 0,4,8,12

    // acc2[i][n]: f32x2 pair = rows (m0+2i, m0+2i+1), column n0+n
    unsigned long long acc2[4][8];
#pragma unroll
    for (int i = 0; i < 4; ++i)
#pragma unroll
        for (int n = 0; n < 8; ++n) acc2[i][n] = 0ull;

    for (int k0 = 0; k0 < INDIM; k0 += BK) {
#pragma unroll
        for (int h = 0; h < 2; ++h) {
            const int row = lrow + h * 64;
            float4 a = *reinterpret_cast<const float4*>(x + (size_t)(mb + row) * INDIM + k0 + lk);
            As[(lk + 0) * LDP + row] = a.x;
            As[(lk + 1) * LDP + row] = a.y;
            As[(lk + 2) * LDP + row] = a.z;
            As[(lk + 3) * LDP + row] = a.w;
            float4 b = *reinterpret_cast<const float4*>(wih + (size_t)(nb + row) * INDIM + k0 + lk);
            Bs[(lk + 0) * LDP + row] = b.x;
            Bs[(lk + 1) * LDP + row] = b.y;
            Bs[(lk + 2) * LDP + row] = b.z;
            Bs[(lk + 3) * LDP + row] = b.w;
        }
        __syncthreads();

#pragma unroll
        for (int k = 0; k < BK; ++k) {
            // A pairs along m, directly as packed u64 from smem
            const ulonglong2* ap = reinterpret_cast<const ulonglong2*>(As + k * LDP + m0);
            ulonglong2 am0 = ap[0];
            ulonglong2 am1 = ap[1];
            unsigned long long av[4] = {am0.x, am0.y, am1.x, am1.y};
            float4 b0 = *reinterpret_cast<const float4*>(Bs + k * LDP + n0);
            float4 b1 = *reinterpret_cast<const float4*>(Bs + k * LDP + n0 + 4);
            unsigned long long bb[8] = {
                pack2(b0.x, b0.x), pack2(b0.y, b0.y), pack2(b0.z, b0.z), pack2(b0.w, b0.w),
                pack2(b1.x, b1.x), pack2(b1.y, b1.y), pack2(b1.z, b1.z), pack2(b1.w, b1.w)};
#pragma unroll
            for (int i = 0; i < 4; ++i)
#pragma unroll
                for (int n = 0; n < 8; ++n)
                    fma2(acc2[i][n], av[i], bb[n]);
        }
        __syncthreads();
    }

    float bia[8];
#pragma unroll
    for (int n = 0; n < 8; ++n)
        bia[n] = __ldg(bih + nb + n0 + n) + __ldg(bhh + nb + n0 + n);

#pragma unroll
    for (int i = 0; i < 4; ++i) {
        float lo[8], hi[8];
#pragma unroll
        for (int n = 0; n < 8; ++n) unpack2(acc2[i][n], lo[n], hi[n]);
        float* dst0 = g_xw + (size_t)(mb + m0 + 2 * i) * HID + nb + n0;
        float* dst1 = dst0 + HID;
        float4 o;
        o.x = lo[0] + bia[0]; o.y = lo[1] + bia[1]; o.z = lo[2] + bia[2]; o.w = lo[3] + bia[3];
        *reinterpret_cast<float4*>(dst0) = o;
        o.x = lo[4] + bia[4]; o.y = lo[5] + bia[5]; o.z = lo[6] + bia[6]; o.w = lo[7] + bia[7];
        *reinterpret_cast<float4*>(dst0 + 4) = o;
        o.x = hi[0] + bia[0]; o.y = hi[1] + bia[1]; o.z = hi[2] + bia[2]; o.w = hi[3] + bia[3];
        *reinterpret_cast<float4*>(dst1) = o;
        o.x = hi[4] + bia[4]; o.y = hi[5] + bia[5]; o.z = hi[6] + bia[6]; o.w = hi[7] + bia[7];
        *reinterpret_cast<float4*>(dst1 + 4) = o;
    }
}

// ---------------- Phase 2: recurrence ----------------
// h_t[b,j] = relu(xw[t,b,j] + sum_k W_hh[j,k] * h_{t-1}[b,k])
// 16 clusters x 8 CTAs. CTA rank r owns j in [r*64, r*64+64); its W_hh slice
// lives in REGISTERS (64 u64 = 128 k-values per thread, fixed j per thread).
// h exchange: each CTA vector-scatters its 1KB slice into all 8 cluster CTAs'
// double-buffered hb via st.shared::cluster, then one cluster barrier per step
// (arrive=release, wait=acquire orders the DSMEM stores).

#define CL_SIZE 8

__global__ void __launch_bounds__(256, 1) __cluster_dims__(CL_SIZE, 1, 1)
rnn_kernel(const float* __restrict__ whh, float* __restrict__ out)
{
    __shared__ float hb[2][4][HID];     // double-buffered h, [buf][batch][k]  16KB
    __shared__ float red[4][4][64];     // k-partials [kp][b][j]                4KB
    __shared__ float stage[4][64];      // staging for vector scatter           1KB

    const int tid  = threadIdx.x;
    const int rank = blockIdx.x & (CL_SIZE - 1);
    const int cl   = blockIdx.x >> 3;
    const int j0   = rank * 64;
    const int b0   = cl * 4;
    const int kp   = tid >> 6;      // k partition 0..3 (also batch in tail)
    const int j    = tid & 63;
    const int jg   = j0 + j;
    const int gb   = b0 + kp;

    // W_hh[jg][kp*128 .. kp*128+128) -> 64 packed u64 registers (k-pairs)
    unsigned long long w2[64];
    {
        const unsigned long long* wrow =
            reinterpret_cast<const unsigned long long*>(whh + (size_t)jg * HID + kp * 128);
#pragma unroll
        for (int i = 0; i < 64; ++i) w2[i] = wrow[i];
    }

    // zero the t=0 read buffer (hb[1]); hb[0] is fully written by t=0 scatter
    for (int i = tid; i < 4 * HID; i += 256) (&hb[1][0][0])[i] = 0.f;

    // remote smem base of hb in every cluster CTA
    unsigned hbL = (unsigned)__cvta_generic_to_shared(&hb[0][0][0]);
    unsigned remBase[CL_SIZE];
#pragma unroll
    for (int r = 0; r < CL_SIZE; ++r)
        asm("mapa.shared::cluster.u32 %0, %1, %2;" : "=r"(remBase[r]) : "r"(hbL), "r"(r));

    float xw = g_xw[(size_t)gb * HID + jg];   // xw for t=0

    __syncthreads();
    asm volatile("barrier.cluster.arrive.aligned;" ::: "memory");
    asm volatile("barrier.cluster.wait.aligned;" ::: "memory");

    for (int t = 0; t < T_STEPS; ++t) {
        const int rb = (t + 1) & 1;   // holds h_{t-1}
        const int wb = t & 1;         // receives h_t

        // partial GEMV over k in [kp*128, kp*128+128), 4 batches, f32x2 along k
        unsigned long long a0 = 0, a1 = 0, a2 = 0, a3 = 0;
        const ulonglong2* p0 = reinterpret_cast<const ulonglong2*>(&hb[rb][0][kp * 128]);
        const ulonglong2* p1 = reinterpret_cast<const ulonglong2*>(&hb[rb][1][kp * 128]);
        const ulonglong2* p2 = reinterpret_cast<const ulonglong2*>(&hb[rb][2][kp * 128]);
        const ulonglong2* p3 = reinterpret_cast<const ulonglong2*>(&hb[rb][3][kp * 128]);
#pragma unroll
        for (int q = 0; q < 32; ++q) {
            ulonglong2 v0 = p0[q], v1 = p1[q], v2 = p2[q], v3 = p3[q];
            fma2(a0, w2[2 * q],     v0.x);
            fma2(a0, w2[2 * q + 1], v0.y);
            fma2(a1, w2[2 * q],     v1.x);
            fma2(a1, w2[2 * q + 1], v1.y);
            fma2(a2, w2[2 * q],     v2.x);
            fma2(a2, w2[2 * q + 1], v2.y);
            fma2(a3, w2[2 * q],     v3.x);
            fma2(a3, w2[2 * q + 1], v3.y);
        }
        float x0, y0, x1, y1, x2, y2, x3, y3;
        unpack2(a0, x0, y0); unpack2(a1, x1, y1);
        unpack2(a2, x2, y2); unpack2(a3, x3, y3);
        red[kp][0][j] = x0 + y0;
        red[kp][1][j] = x1 + y1;
        red[kp][2][j] = x2 + y2;
        red[kp][3][j] = x3 + y3;
        __syncthreads();

        // finalize (batch kp, column jg)
        float s = red[0][kp][j] + red[1][kp][j] + red[2][kp][j] + red[3][kp][j];
        float v = fmaxf(xw + s, 0.f);
        out[((size_t)t * BATCH + gb) * HID + jg] = v;

        if (t == T_STEPS - 1) {
            out[(size_t)T_STEPS * BATCH * HID + (size_t)gb * HID + jg] = v;
        } else {
            // stage our 4x64 slice locally, then vector-scatter to all 8 CTAs
            stage[kp][j] = v;
            __syncthreads();
            const int dr = tid >> 5;       // destination rank 0..7
            const int c0 = tid & 31;
#pragma unroll
            for (int h = 0; h < 2; ++h) {
                const int c  = c0 + h * 32;   // chunk 0..63
                const int b  = c >> 4;        // batch 0..3
                const int jq = c & 15;        // j quad
                float4 val = *reinterpret_cast<const float4*>(&stage[b][jq * 4]);
                unsigned dst = remBase[dr] + (((wb * 4 + b) * HID + j0 + jq * 4) << 2);
                asm volatile("st.shared::cluster.v4.f32 [%0], {%1,%2,%3,%4};"
                             :: "r"(dst), "f"(val.x), "f"(val.y), "f"(val.z), "f"(val.w)
                             : "memory");
            }
            asm volatile("barrier.cluster.arrive.aligned;" ::: "memory");
            // independent prefetch between arrive and wait
            float nxw = g_xw[((size_t)(t + 1) * BATCH + gb) * HID + jg];
            asm volatile("barrier.cluster.wait.aligned;" ::: "memory");
            xw = nxw;
        }
    }
    // drain: no CTA may exit while peers could still write its smem
    asm volatile("barrier.cluster.arrive.aligned;" ::: "memory");
    asm volatile("barrier.cluster.wait.aligned;" ::: "memory");
}

// ---------------- launch ----------------
extern "C" void kernel_launch(void* const* d_in, const int* in_sizes, int n_in,
                              void* d_out, int out_size)
{
    (void)in_sizes; (void)n_in; (void)out_size;
    const float* x   = (const float*)d_in[0];
    const float* wih = (const float*)d_in[1];
    const float* whh = (const float*)d_in[2];
    const float* bih = (const float*)d_in[3];
    const float* bhh = (const float*)d_in[4];
    float* out = (float*)d_out;

    dim3 g1((T_STEPS * BATCH) / BM, HID / BN);   // (256, 4)
    xw_gemm_kernel<<<g1, 256>>>(x, wih, bih, bhh);

    rnn_kernel<<<(BATCH / 4) * CL_SIZE, 256>>>(whh, out);   // 128 CTAs, 16 clusters
}

// round 10
// speedup vs baseline: 1.3755x; 1.0005x over previous
#include <cuda_runtime.h>
#include <cstdint>

// Problem dims
#define T_STEPS 512
#define BATCH   64
#define INDIM   256
#define HID     512

// ---------------- f32x2 helpers (FFMA2 only reachable via PTX) ----------------
__device__ __forceinline__ unsigned long long pack2(float x, float y) {
    unsigned long long r;
    asm("mov.b64 %0, {%1,%2};" : "=l"(r) : "f"(x), "f"(y));
    return r;
}
__device__ __forceinline__ void unpack2(unsigned long long v, float& x, float& y) {
    asm("mov.b64 {%0,%1}, %2;" : "=f"(x), "=f"(y) : "l"(v));
}
__device__ __forceinline__ void fma2(unsigned long long& d, unsigned long long a,
                                     unsigned long long b) {
    asm("fma.rn.f32x2 %0, %1, %2, %0;" : "+l"(d) : "l"(a), "l"(b));
}

// ---------------- Phase 1: xw = x @ W_ih^T + bias_ih + bias_hh ----------------
// C[m,n] = sum_k x[m,k] * W_ih[n,k],  m = t*64+b (32768), n (512), k (256)

__device__ float g_xw[(size_t)T_STEPS * BATCH * HID];   // 64 MB static scratch

#define BM 128
#define BN 128
#define BK 16
#define LDP 132   // padded row stride in floats (16B aligned: 132*4=528=33*16)

__global__ void __launch_bounds__(256, 2)
xw_gemm_kernel(const float* __restrict__ x, const float* __restrict__ wih,
               const float* __restrict__ bih, const float* __restrict__ bhh)
{
    __shared__ float As[BK * LDP];   // [k][m]
    __shared__ float Bs[BK * LDP];   // [k][n]

    const int tid = threadIdx.x;
    const int mb = blockIdx.x * BM;
    const int nb = blockIdx.y * BN;

    const int tx = tid & 15;        // n dir
    const int ty = tid >> 4;        // m dir
    const int m0 = ty * 8;
    const int n0 = tx * 8;

    const int lrow = tid >> 2;          // 0..63
    const int lk   = (tid & 3) * 4;     // 0,4,8,12

    // acc2[i][n]: f32x2 pair = rows (m0+2i, m0+2i+1), column n0+n
    unsigned long long acc2[4][8];
#pragma unroll
    for (int i = 0; i < 4; ++i)
#pragma unroll
        for (int n = 0; n < 8; ++n) acc2[i][n] = 0ull;

    for (int k0 = 0; k0 < INDIM; k0 += BK) {
#pragma unroll
        for (int h = 0; h < 2; ++h) {
            const int row = lrow + h * 64;
            float4 a = *reinterpret_cast<const float4*>(x + (size_t)(mb + row) * INDIM + k0 + lk);
            As[(lk + 0) * LDP + row] = a.x;
            As[(lk + 1) * LDP + row] = a.y;
            As[(lk + 2) * LDP + row] = a.z;
            As[(lk + 3) * LDP + row] = a.w;
            float4 b = *reinterpret_cast<const float4*>(wih + (size_t)(nb + row) * INDIM + k0 + lk);
            Bs[(lk + 0) * LDP + row] = b.x;
            Bs[(lk + 1) * LDP + row] = b.y;
            Bs[(lk + 2) * LDP + row] = b.z;
            Bs[(lk + 3) * LDP + row] = b.w;
        }
        __syncthreads();

#pragma unroll
        for (int k = 0; k < BK; ++k) {
            // A pairs along m, directly as packed u64 from smem
            const ulonglong2* ap = reinterpret_cast<const ulonglong2*>(As + k * LDP + m0);
            ulonglong2 am0 = ap[0];
            ulonglong2 am1 = ap[1];
            unsigned long long av[4] = {am0.x, am0.y, am1.x, am1.y};
            float4 b0 = *reinterpret_cast<const float4*>(Bs + k * LDP + n0);
            float4 b1 = *reinterpret_cast<const float4*>(Bs + k * LDP + n0 + 4);
            unsigned long long bb[8] = {
                pack2(b0.x, b0.x), pack2(b0.y, b0.y), pack2(b0.z, b0.z), pack2(b0.w, b0.w),
                pack2(b1.x, b1.x), pack2(b1.y, b1.y), pack2(b1.z, b1.z), pack2(b1.w, b1.w)};
#pragma unroll
            for (int i = 0; i < 4; ++i)
#pragma unroll
                for (int n = 0; n < 8; ++n)
                    fma2(acc2[i][n], av[i], bb[n]);
        }
        __syncthreads();
    }

    float bia[8];
#pragma unroll
    for (int n = 0; n < 8; ++n)
        bia[n] = __ldg(bih + nb + n0 + n) + __ldg(bhh + nb + n0 + n);

#pragma unroll
    for (int i = 0; i < 4; ++i) {
        float lo[8], hi[8];
#pragma unroll
        for (int n = 0; n < 8; ++n) unpack2(acc2[i][n], lo[n], hi[n]);
        float* dst0 = g_xw + (size_t)(mb + m0 + 2 * i) * HID + nb + n0;
        float* dst1 = dst0 + HID;
        float4 o;
        o.x = lo[0] + bia[0]; o.y = lo[1] + bia[1]; o.z = lo[2] + bia[2]; o.w = lo[3] + bia[3];
        *reinterpret_cast<float4*>(dst0) = o;
        o.x = lo[4] + bia[4]; o.y = lo[5] + bia[5]; o.z = lo[6] + bia[6]; o.w = lo[7] + bia[7];
        *reinterpret_cast<float4*>(dst0 + 4) = o;
        o.x = hi[0] + bia[0]; o.y = hi[1] + bia[1]; o.z = hi[2] + bia[2]; o.w = hi[3] + bia[3];
        *reinterpret_cast<float4*>(dst1) = o;
        o.x = hi[4] + bia[4]; o.y = hi[5] + bia[5]; o.z = hi[6] + bia[6]; o.w = hi[7] + bia[7];
        *reinterpret_cast<float4*>(dst1 + 4) = o;
    }
}

// ---------------- Phase 2: recurrence ----------------
// h_t[b,j] = relu(xw[t,b,j] + sum_k W_hh[j,k] * h_{t-1}[b,k])
// 16 clusters x 8 CTAs. CTA rank r owns j in [r*64, r*64+64); its W_hh slice
// lives in REGISTERS (64 u64 = 128 k-values per thread, fixed j per thread).
// h exchange: each CTA vector-scatters its 1KB slice into all 8 cluster CTAs'
// double-buffered hb via st.shared::cluster, then one cluster barrier per step
// (arrive=release, wait=acquire orders the DSMEM stores).

#define CL_SIZE 8

__global__ void __launch_bounds__(256, 1) __cluster_dims__(CL_SIZE, 1, 1)
rnn_kernel(const float* __restrict__ whh, float* __restrict__ out)
{
    __shared__ float hb[2][4][HID];     // double-buffered h, [buf][batch][k]  16KB
    __shared__ float red[4][4][64];     // k-partials [kp][b][j]                4KB
    __shared__ float stage[4][64];      // staging for vector scatter           1KB

    const int tid  = threadIdx.x;
    const int rank = blockIdx.x & (CL_SIZE - 1);
    const int cl   = blockIdx.x >> 3;
    const int j0   = rank * 64;
    const int b0   = cl * 4;
    const int kp   = tid >> 6;      // k partition 0..3 (also batch in tail)
    const int j    = tid & 63;
    const int jg   = j0 + j;
    const int gb   = b0 + kp;

    // W_hh[jg][kp*128 .. kp*128+128) -> 64 packed u64 registers (k-pairs)
    unsigned long long w2[64];
    {
        const unsigned long long* wrow =
            reinterpret_cast<const unsigned long long*>(whh + (size_t)jg * HID + kp * 128);
#pragma unroll
        for (int i = 0; i < 64; ++i) w2[i] = wrow[i];
    }

    // zero the t=0 read buffer (hb[1]); hb[0] is fully written by t=0 scatter
    for (int i = tid; i < 4 * HID; i += 256) (&hb[1][0][0])[i] = 0.f;

    // remote smem base of hb in every cluster CTA
    unsigned hbL = (unsigned)__cvta_generic_to_shared(&hb[0][0][0]);
    unsigned remBase[CL_SIZE];
#pragma unroll
    for (int r = 0; r < CL_SIZE; ++r)
        asm("mapa.shared::cluster.u32 %0, %1, %2;" : "=r"(remBase[r]) : "r"(hbL), "r"(r));

    float xw = g_xw[(size_t)gb * HID + jg];   // xw for t=0

    __syncthreads();
    asm volatile("barrier.cluster.arrive.aligned;" ::: "memory");
    asm volatile("barrier.cluster.wait.aligned;" ::: "memory");

    for (int t = 0; t < T_STEPS; ++t) {
        const int rb = (t + 1) & 1;   // holds h_{t-1}
        const int wb = t & 1;         // receives h_t

        // partial GEMV over k in [kp*128, kp*128+128), 4 batches, f32x2 along k
        unsigned long long a0 = 0, a1 = 0, a2 = 0, a3 = 0;
        const ulonglong2* p0 = reinterpret_cast<const ulonglong2*>(&hb[rb][0][kp * 128]);
        const ulonglong2* p1 = reinterpret_cast<const ulonglong2*>(&hb[rb][1][kp * 128]);
        const ulonglong2* p2 = reinterpret_cast<const ulonglong2*>(&hb[rb][2][kp * 128]);
        const ulonglong2* p3 = reinterpret_cast<const ulonglong2*>(&hb[rb][3][kp * 128]);
#pragma unroll
        for (int q = 0; q < 32; ++q) {
            ulonglong2 v0 = p0[q], v1 = p1[q], v2 = p2[q], v3 = p3[q];
            fma2(a0, w2[2 * q],     v0.x);
            fma2(a0, w2[2 * q + 1], v0.y);
            fma2(a1, w2[2 * q],     v1.x);
            fma2(a1, w2[2 * q + 1], v1.y);
            fma2(a2, w2[2 * q],     v2.x);
            fma2(a2, w2[2 * q + 1], v2.y);
            fma2(a3, w2[2 * q],     v3.x);
            fma2(a3, w2[2 * q + 1], v3.y);
        }
        float x0, y0, x1, y1, x2, y2, x3, y3;
        unpack2(a0, x0, y0); unpack2(a1, x1, y1);
        unpack2(a2, x2, y2); unpack2(a3, x3, y3);
        red[kp][0][j] = x0 + y0;
        red[kp][1][j] = x1 + y1;
        red[kp][2][j] = x2 + y2;
        red[kp][3][j] = x3 + y3;
        __syncthreads();

        // finalize (batch kp, column jg)
        float s = red[0][kp][j] + red[1][kp][j] + red[2][kp][j] + red[3][kp][j];
        float v = fmaxf(xw + s, 0.f);
        out[((size_t)t * BATCH + gb) * HID + jg] = v;

        if (t == T_STEPS - 1) {
            out[(size_t)T_STEPS * BATCH * HID + (size_t)gb * HID + jg] = v;
        } else {
            // stage our 4x64 slice locally, then vector-scatter to all 8 CTAs
            stage[kp][j] = v;
            __syncthreads();
            const int dr = tid >> 5;       // destination rank 0..7
            const int c0 = tid & 31;
#pragma unroll
            for (int h = 0; h < 2; ++h) {
                const int c  = c0 + h * 32;   // chunk 0..63
                const int b  = c >> 4;        // batch 0..3
                const int jq = c & 15;        // j quad
                float4 val = *reinterpret_cast<const float4*>(&stage[b][jq * 4]);
                unsigned dst = remBase[dr] + (((wb * 4 + b) * HID + j0 + jq * 4) << 2);
                asm volatile("st.shared::cluster.v4.f32 [%0], {%1,%2,%3,%4};"
                             :: "r"(dst), "f"(val.x), "f"(val.y), "f"(val.z), "f"(val.w)
                             : "memory");
            }
            asm volatile("barrier.cluster.arrive.aligned;" ::: "memory");
            // independent prefetch between arrive and wait
            float nxw = g_xw[((size_t)(t + 1) * BATCH + gb) * HID + jg];
            asm volatile("barrier.cluster.wait.aligned;" ::: "memory");
            xw = nxw;
        }
    }
    // drain: no CTA may exit while peers could still write its smem
    asm volatile("barrier.cluster.arrive.aligned;" ::: "memory");
    asm volatile("barrier.cluster.wait.aligned;" ::: "memory");
}

// ---------------- launch ----------------
extern "C" void kernel_launch(void* const* d_in, const int* in_sizes, int n_in,
                              void* d_out, int out_size)
{
    (void)in_sizes; (void)n_in; (void)out_size;
    const float* x   = (const float*)d_in[0];
    const float* wih = (const float*)d_in[1];
    const float* whh = (const float*)d_in[2];
    const float* bih = (const float*)d_in[3];
    const float* bhh = (const float*)d_in[4];
    float* out = (float*)d_out;

    dim3 g1((T_STEPS * BATCH) / BM, HID / BN);   // (256, 4)
    xw_gemm_kernel<<<g1, 256>>>(x, wih, bih, bhh);

    rnn_kernel<<<(BATCH / 4) * CL_SIZE, 256>>>(whh, out);   // 128 CTAs, 16 clusters
}

// round 11
// speedup vs baseline: 1.3758x; 1.0002x over previous
#include <cuda_runtime.h>
#include <cstdint>

// Problem dims
#define T_STEPS 512
#define BATCH   64
#define INDIM   256
#define HID     512

// ---------------- f32x2 helpers (FFMA2 only reachable via PTX) ----------------
__device__ __forceinline__ unsigned long long pack2(float x, float y) {
    unsigned long long r;
    asm("mov.b64 %0, {%1,%2};" : "=l"(r) : "f"(x), "f"(y));
    return r;
}
__device__ __forceinline__ void unpack2(unsigned long long v, float& x, float& y) {
    asm("mov.b64 {%0,%1}, %2;" : "=f"(x), "=f"(y) : "l"(v));
}
__device__ __forceinline__ void fma2(unsigned long long& d, unsigned long long a,
                                     unsigned long long b) {
    asm("fma.rn.f32x2 %0, %1, %2, %0;" : "+l"(d) : "l"(a), "l"(b));
}

// ---------------- Phase 1: xw = x @ W_ih^T + bias_ih + bias_hh ----------------
// C[m,n] = sum_k x[m,k] * W_ih[n,k],  m = t*64+b (32768), n (512), k (256)

__device__ float g_xw[(size_t)T_STEPS * BATCH * HID];   // 64 MB static scratch

#define BM 128
#define BN 128
#define BK 16
#define LDP 132   // padded row stride in floats (16B aligned: 132*4=528=33*16)

__global__ void __launch_bounds__(256, 2)
xw_gemm_kernel(const float* __restrict__ x, const float* __restrict__ wih,
               const float* __restrict__ bih, const float* __restrict__ bhh)
{
    __shared__ float As[BK * LDP];   // [k][m]
    __shared__ float Bs[BK * LDP];   // [k][n]

    const int tid = threadIdx.x;
    const int mb = blockIdx.x * BM;
    const int nb = blockIdx.y * BN;

    const int tx = tid & 15;        // n dir
    const int ty = tid >> 4;        // m dir
    const int m0 = ty * 8;
    const int n0 = tx * 8;

    const int lrow = tid >> 2;          // 0..63
    const int lk   = (tid & 3) * 4;     // 0,4,8,12

    // acc2[i][n]: f32x2 pair = rows (m0+2i, m0+2i+1), column n0+n
    unsigned long long acc2[4][8];
#pragma unroll
    for (int i = 0; i < 4; ++i)
#pragma unroll
        for (int n = 0; n < 8; ++n) acc2[i][n] = 0ull;

    for (int k0 = 0; k0 < INDIM; k0 += BK) {
#pragma unroll
        for (int h = 0; h < 2; ++h) {
            const int row = lrow + h * 64;
            float4 a = *reinterpret_cast<const float4*>(x + (size_t)(mb + row) * INDIM + k0 + lk);
            As[(lk + 0) * LDP + row] = a.x;
            As[(lk + 1) * LDP + row] = a.y;
            As[(lk + 2) * LDP + row] = a.z;
            As[(lk + 3) * LDP + row] = a.w;
            float4 b = *reinterpret_cast<const float4*>(wih + (size_t)(nb + row) * INDIM + k0 + lk);
            Bs[(lk + 0) * LDP + row] = b.x;
            Bs[(lk + 1) * LDP + row] = b.y;
            Bs[(lk + 2) * LDP + row] = b.z;
            Bs[(lk + 3) * LDP + row] = b.w;
        }
        __syncthreads();

#pragma unroll
        for (int k = 0; k < BK; ++k) {
            // A pairs along m, directly as packed u64 from smem
            const ulonglong2* ap = reinterpret_cast<const ulonglong2*>(As + k * LDP + m0);
            ulonglong2 am0 = ap[0];
            ulonglong2 am1 = ap[1];
            unsigned long long av[4] = {am0.x, am0.y, am1.x, am1.y};
            float4 b0 = *reinterpret_cast<const float4*>(Bs + k * LDP + n0);
            float4 b1 = *reinterpret_cast<const float4*>(Bs + k * LDP + n0 + 4);
            unsigned long long bb[8] = {
                pack2(b0.x, b0.x), pack2(b0.y, b0.y), pack2(b0.z, b0.z), pack2(b0.w, b0.w),
                pack2(b1.x, b1.x), pack2(b1.y, b1.y), pack2(b1.z, b1.z), pack2(b1.w, b1.w)};
#pragma unroll
            for (int i = 0; i < 4; ++i)
#pragma unroll
                for (int n = 0; n < 8; ++n)
                    fma2(acc2[i][n], av[i], bb[n]);
        }
        __syncthreads();
    }

    float bia[8];
#pragma unroll
    for (int n = 0; n < 8; ++n)
        bia[n] = __ldg(bih + nb + n0 + n) + __ldg(bhh + nb + n0 + n);

#pragma unroll
    for (int i = 0; i < 4; ++i) {
        float lo[8], hi[8];
#pragma unroll
        for (int n = 0; n < 8; ++n) unpack2(acc2[i][n], lo[n], hi[n]);
        float* dst0 = g_xw + (size_t)(mb + m0 + 2 * i) * HID + nb + n0;
        float* dst1 = dst0 + HID;
        float4 o;
        o.x = lo[0] + bia[0]; o.y = lo[1] + bia[1]; o.z = lo[2] + bia[2]; o.w = lo[3] + bia[3];
        *reinterpret_cast<float4*>(dst0) = o;
        o.x = lo[4] + bia[4]; o.y = lo[5] + bia[5]; o.z = lo[6] + bia[6]; o.w = lo[7] + bia[7];
        *reinterpret_cast<float4*>(dst0 + 4) = o;
        o.x = hi[0] + bia[0]; o.y = hi[1] + bia[1]; o.z = hi[2] + bia[2]; o.w = hi[3] + bia[3];
        *reinterpret_cast<float4*>(dst1) = o;
        o.x = hi[4] + bia[4]; o.y = hi[5] + bia[5]; o.z = hi[6] + bia[6]; o.w = hi[7] + bia[7];
        *reinterpret_cast<float4*>(dst1 + 4) = o;
    }
}

// ---------------- Phase 2: recurrence ----------------
// h_t[b,j] = relu(xw[t,b,j] + sum_k W_hh[j,k] * h_{t-1}[b,k])
// 16 clusters x 8 CTAs. CTA rank r owns j in [r*64, r*64+64); its W_hh slice
// lives in REGISTERS (64 u64 = 128 k-values per thread, fixed j per thread).
// h exchange: each CTA vector-scatters its 1KB slice into all 8 cluster CTAs'
// double-buffered hb via st.shared::cluster, then one cluster barrier per step
// (arrive=release, wait=acquire orders the DSMEM stores).

#define CL_SIZE 8

__global__ void __launch_bounds__(256, 1) __cluster_dims__(CL_SIZE, 1, 1)
rnn_kernel(const float* __restrict__ whh, float* __restrict__ out)
{
    __shared__ float hb[2][4][HID];     // double-buffered h, [buf][batch][k]  16KB
    __shared__ float red[4][4][64];     // k-partials [kp][b][j]                4KB
    __shared__ float stage[4][64];      // staging for vector scatter           1KB

    const int tid  = threadIdx.x;
    const int rank = blockIdx.x & (CL_SIZE - 1);
    const int cl   = blockIdx.x >> 3;
    const int j0   = rank * 64;
    const int b0   = cl * 4;
    const int kp   = tid >> 6;      // k partition 0..3 (also batch in tail)
    const int j    = tid & 63;
    const int jg   = j0 + j;
    const int gb   = b0 + kp;

    // W_hh[jg][kp*128 .. kp*128+128) -> 64 packed u64 registers (k-pairs)
    unsigned long long w2[64];
    {
        const unsigned long long* wrow =
            reinterpret_cast<const unsigned long long*>(whh + (size_t)jg * HID + kp * 128);
#pragma unroll
        for (int i = 0; i < 64; ++i) w2[i] = wrow[i];
    }

    // zero the t=0 read buffer (hb[1]); hb[0] is fully written by t=0 scatter
    for (int i = tid; i < 4 * HID; i += 256) (&hb[1][0][0])[i] = 0.f;

    // remote smem base of hb in every cluster CTA
    unsigned hbL = (unsigned)__cvta_generic_to_shared(&hb[0][0][0]);
    unsigned remBase[CL_SIZE];
#pragma unroll
    for (int r = 0; r < CL_SIZE; ++r)
        asm("mapa.shared::cluster.u32 %0, %1, %2;" : "=r"(remBase[r]) : "r"(hbL), "r"(r));

    float xw = g_xw[(size_t)gb * HID + jg];   // xw for t=0

    __syncthreads();
    asm volatile("barrier.cluster.arrive.aligned;" ::: "memory");
    asm volatile("barrier.cluster.wait.aligned;" ::: "memory");

    for (int t = 0; t < T_STEPS; ++t) {
        const int rb = (t + 1) & 1;   // holds h_{t-1}
        const int wb = t & 1;         // receives h_t

        // partial GEMV over k in [kp*128, kp*128+128), 4 batches, f32x2 along k
        unsigned long long a0 = 0, a1 = 0, a2 = 0, a3 = 0;
        const ulonglong2* p0 = reinterpret_cast<const ulonglong2*>(&hb[rb][0][kp * 128]);
        const ulonglong2* p1 = reinterpret_cast<const ulonglong2*>(&hb[rb][1][kp * 128]);
        const ulonglong2* p2 = reinterpret_cast<const ulonglong2*>(&hb[rb][2][kp * 128]);
        const ulonglong2* p3 = reinterpret_cast<const ulonglong2*>(&hb[rb][3][kp * 128]);
#pragma unroll
        for (int q = 0; q < 32; ++q) {
            ulonglong2 v0 = p0[q], v1 = p1[q], v2 = p2[q], v3 = p3[q];
            fma2(a0, w2[2 * q],     v0.x);
            fma2(a0, w2[2 * q + 1], v0.y);
            fma2(a1, w2[2 * q],     v1.x);
            fma2(a1, w2[2 * q + 1], v1.y);
            fma2(a2, w2[2 * q],     v2.x);
            fma2(a2, w2[2 * q + 1], v2.y);
            fma2(a3, w2[2 * q],     v3.x);
            fma2(a3, w2[2 * q + 1], v3.y);
        }
        float x0, y0, x1, y1, x2, y2, x3, y3;
        unpack2(a0, x0, y0); unpack2(a1, x1, y1);
        unpack2(a2, x2, y2); unpack2(a3, x3, y3);
        red[kp][0][j] = x0 + y0;
        red[kp][1][j] = x1 + y1;
        red[kp][2][j] = x2 + y2;
        red[kp][3][j] = x3 + y3;
        __syncthreads();

        // finalize (batch kp, column jg)
        float s = red[0][kp][j] + red[1][kp][j] + red[2][kp][j] + red[3][kp][j];
        float v = fmaxf(xw + s, 0.f);
        out[((size_t)t * BATCH + gb) * HID + jg] = v;

        if (t == T_STEPS - 1) {
            out[(size_t)T_STEPS * BATCH * HID + (size_t)gb * HID + jg] = v;
        } else {
            // stage our 4x64 slice locally, then vector-scatter to all 8 CTAs
            stage[kp][j] = v;
            __syncthreads();
            const int dr = tid >> 5;       // destination rank 0..7
            const int c0 = tid & 31;
#pragma unroll
            for (int h = 0; h < 2; ++h) {
                const int c  = c0 + h * 32;   // chunk 0..63
                const int b  = c >> 4;        // batch 0..3
                const int jq = c & 15;        // j quad
                float4 val = *reinterpret_cast<const float4*>(&stage[b][jq * 4]);
                unsigned dst = remBase[dr] + (((wb * 4 + b) * HID + j0 + jq * 4) << 2);
                asm volatile("st.shared::cluster.v4.f32 [%0], {%1,%2,%3,%4};"
                             :: "r"(dst), "f"(val.x), "f"(val.y), "f"(val.z), "f"(val.w)
                             : "memory");
            }
            asm volatile("barrier.cluster.arrive.aligned;" ::: "memory");
            // independent prefetch between arrive and wait
            float nxw = g_xw[((size_t)(t + 1) * BATCH + gb) * HID + jg];
            asm volatile("barrier.cluster.wait.aligned;" ::: "memory");
            xw = nxw;
        }
    }
    // drain: no CTA may exit while peers could still write its smem
    asm volatile("barrier.cluster.arrive.aligned;" ::: "memory");
    asm volatile("barrier.cluster.wait.aligned;" ::: "memory");
}

// ---------------- launch ----------------
extern "C" void kernel_launch(void* const* d_in, const int* in_sizes, int n_in,
                              void* d_out, int out_size)
{
    (void)in_sizes; (void)n_in; (void)out_size;
    const float* x   = (const float*)d_in[0];
    const float* wih = (const float*)d_in[1];
    const float* whh = (const float*)d_in[2];
    const float* bih = (const float*)d_in[3];
    const float* bhh = (const float*)d_in[4];
    float* out = (float*)d_out;

    dim3 g1((T_STEPS * BATCH) / BM, HID / BN);   // (256, 4)
    xw_gemm_kernel<<<g1, 256>>>(x, wih, bih, bhh);

    rnn_kernel<<<(BATCH / 4) * CL_SIZE, 256>>>(whh, out);   // 128 CTAs, 16 clusters
}